// round 2
// baseline (speedup 1.0000x reference)
#include <cuda_runtime.h>
#include <math.h>

// Problem constants
#define BB 16
#define DD 128
#define LL 4096
#define CL 128          // chunk length
#define NCH 32          // chunks per batch (LL/CL)
#define NSTATE 2
#define DTR 8

// ---------------- scratch (static device globals; no allocation) ----------------
__device__ float g_xspre[BB * DD * LL];   // (b,d,l) conv input (xz first half)
__device__ float g_z    [BB * DD * LL];   // (b,d,l) gate branch (raw)
__device__ float g_S    [BB * DD * LL];   // (b,d,l) cumsum of dt within chunk
__device__ float g_yloc [BB * DD * LL];   // (b,d,l) local-scan y + xs*D
__device__ float g_Cm   [BB * LL * NSTATE];
__device__ float g_sumdt[BB * NCH * DD];
__device__ float g_hend [BB * NCH * DD * NSTATE];
__device__ float g_h0   [BB * NCH * DD * NSTATE];

// ---------------- K1: in-projection GEMM  xz = x @ W_in^T ----------------
// grid (512, 2): blockIdx.x = token tile (128 tokens), blockIdx.y = output half
// smem: Xs[128][132] (k-major x tile), Ws[128][132] (k-major weight tile)
__global__ __launch_bounds__(256) void k1_inproj(const float* __restrict__ x1,
                                                 const float* __restrict__ W_in)
{
    extern __shared__ float sm[];
    float* Xs = sm;                  // Xs[k*132 + l]
    float* Ws = sm + 128 * 132;      // Ws[k*132 + e]
    const int blk  = blockIdx.x;
    const int half = blockIdx.y;
    const int b  = blk >> 5;
    const int l0 = (blk & 31) << 7;
    const int tid = threadIdx.x;

    const float* xb = x1 + (size_t)b * DD * LL;
    for (int j = tid; j < 128 * 128; j += 256) {
        int k = j >> 7, l = j & 127;
        Xs[k * 132 + l] = xb[k * LL + l0 + l];
    }
    const float* Wh = W_in + half * 128 * 128;
    for (int j = tid; j < 128 * 128; j += 256) {
        int e = j >> 7, k = j & 127;
        Ws[k * 132 + e] = Wh[e * 128 + k];
    }
    __syncthreads();

    const int tx = tid & 15, ty = tid >> 4;
    float acc[8][8];                  // acc[jj(e)][ii(l)]
#pragma unroll
    for (int jj = 0; jj < 8; jj++)
#pragma unroll
        for (int ii = 0; ii < 8; ii++) acc[jj][ii] = 0.f;

    const float* Ap = Xs + tx * 8;
    const float* Bp = Ws + ty * 8;
#pragma unroll 4
    for (int k = 0; k < 128; k++) {
        float4 a0 = *(const float4*)(Ap + k * 132);
        float4 a1 = *(const float4*)(Ap + k * 132 + 4);
        float4 w0 = *(const float4*)(Bp + k * 132);
        float4 w1 = *(const float4*)(Bp + k * 132 + 4);
        float a[8] = {a0.x, a0.y, a0.z, a0.w, a1.x, a1.y, a1.z, a1.w};
        float w[8] = {w0.x, w0.y, w0.z, w0.w, w1.x, w1.y, w1.z, w1.w};
#pragma unroll
        for (int jj = 0; jj < 8; jj++)
#pragma unroll
            for (int ii = 0; ii < 8; ii++) acc[jj][ii] += w[jj] * a[ii];
    }
    __syncthreads();

    // stage transposed: Os[e][l] in Xs (now dead)
#pragma unroll
    for (int jj = 0; jj < 8; jj++) {
        float4* p = (float4*)&Xs[(ty * 8 + jj) * 132 + tx * 8];
        p[0] = make_float4(acc[jj][0], acc[jj][1], acc[jj][2], acc[jj][3]);
        p[1] = make_float4(acc[jj][4], acc[jj][5], acc[jj][6], acc[jj][7]);
    }
    __syncthreads();

    float* dst = (half == 0 ? g_xspre : g_z) + (size_t)b * DD * LL + l0;
    for (int j = tid; j < 128 * 128; j += 256) {
        int e = j >> 7, l = j & 127;
        dst[(size_t)e * LL + l] = Xs[e * 132 + l];
    }
}

// ---------------- K2: conv+silu, xproj, dt, local scan per (b, chunk) ----------------
__global__ __launch_bounds__(256) void k2_chunk(const float* __restrict__ conv_w,
                                                const float* __restrict__ conv_b,
                                                const float* __restrict__ W_xproj,
                                                const float* __restrict__ W_dt,
                                                const float* __restrict__ b_dt,
                                                const float* __restrict__ A_log,
                                                const float* __restrict__ D_param)
{
    extern __shared__ float sm[];
    float* sA    = sm;                      // [128][133] xs_pre -> dt -> S
    float* sB    = sA + 128 * 133;          // [128][133] xs -> y_local
    float* sdbl  = sB + 128 * 133;          // [128][13]
    float* swc   = sdbl + 128 * 13;         // conv_w 512
    float* sbc   = swc + 512;               // conv_b 128
    float* swx   = sbc + 128;               // W_xproj 12*128
    float* swd   = swx + 1536;              // W_dt 128*8
    float* sbd   = swd + 1024;              // b_dt 128

    const int tid = threadIdx.x;
    const int b = blockIdx.x >> 5;
    const int c = blockIdx.x & 31;
    const int l0 = c << 7;
    const float* src = g_xspre + (size_t)b * DD * LL;

    // load xs_pre chunk + 3-halo
    for (int j = tid; j < 128 * 131; j += 256) {
        int d = j / 131, i = j - d * 131;
        int idx = l0 - 3 + i;
        sA[d * 133 + i] = (idx >= 0) ? src[d * LL + idx] : 0.f;
    }
    for (int j = tid; j < 512; j += 256) swc[j] = conv_w[j];
    if (tid < 128) sbc[tid] = conv_b[tid];
    for (int j = tid; j < 1536; j += 256) swx[j] = W_xproj[j];
    for (int j = tid; j < 1024; j += 256) swd[j] = W_dt[j];
    if (tid < 128) sbd[tid] = b_dt[tid];
    __syncthreads();

    // depthwise causal conv + bias + silu -> sB[d][l]
    for (int j = tid; j < 128 * 128; j += 256) {
        int d = j >> 7, l = j & 127;
        float v = sbc[d];
        v += swc[d * 4 + 0] * sA[d * 133 + l + 0];
        v += swc[d * 4 + 1] * sA[d * 133 + l + 1];
        v += swc[d * 4 + 2] * sA[d * 133 + l + 2];
        v += swc[d * 4 + 3] * sA[d * 133 + l + 3];
        float sg = 1.f / (1.f + expf(-v));
        sB[d * 133 + l] = v * sg;
    }
    __syncthreads();

    // dbl[l][j] = sum_d xs[d][l] * W_xproj[j][d]   (12 outputs per token)
    for (int task = tid; task < 12 * 128; task += 256) {
        int jrow = task >> 7, l = task & 127;
        const float* wr = swx + jrow * 128;
        float s = 0.f;
#pragma unroll 8
        for (int d = 0; d < 128; d++) s += sB[d * 133 + l] * wr[d];
        sdbl[l * 13 + jrow] = s;
    }
    __syncthreads();

    // write Cm to global (tiny)
    for (int j = tid; j < 256; j += 256) {
        int l = j >> 1, n = j & 1;
        g_Cm[((size_t)b * LL + l0 + l) * 2 + n] = sdbl[l * 13 + 10 + n];
    }

    // dt[d][l] = softplus(dbl[l][0:8] @ W_dt[d] + b_dt[d]) -> sA (xs_pre dead)
    for (int j = tid; j < 128 * 128; j += 256) {
        int d = j >> 7, l = j & 127;
        float v = sbd[d];
        const float* wr = swd + d * 8;
        const float* dr = sdbl + l * 13;
#pragma unroll
        for (int r = 0; r < 8; r++) v += dr[r] * wr[r];
        float sp = (v > 20.f) ? v : log1pf(expf(v));
        sA[d * 133 + l] = sp;
    }
    __syncthreads();

    // local scan: pair of threads per channel (one per state)
    {
        const int d = tid >> 1, n = tid & 1;
        const float An = -expf(A_log[d * 2 + n]);
        const float Dd = D_param[d];
        float h = 0.f, sd = 0.f;
        for (int l = 0; l < 128; l++) {
            float dtv = sA[d * 133 + l];
            sd += dtv;
            float xv = sB[d * 133 + l];
            float Bn = sdbl[l * 13 + 8 + n];
            float Cn = sdbl[l * 13 + 10 + n];
            h = expf(An * dtv) * h + dtv * Bn * xv;
            float yn = Cn * h;
            float yo = __shfl_xor_sync(0xffffffffu, yn, 1);
            if (n == 0) {
                sB[d * 133 + l] = yn + yo + xv * Dd;  // y_local (+ D*xs folded)
                sA[d * 133 + l] = sd;                 // S cumsum
            }
        }
        size_t ci = (size_t)(b * NCH + c) * 128 + d;
        if (n == 0) g_sumdt[ci] = sd;
        g_hend[ci * 2 + n] = h;
    }
    __syncthreads();

    // flush S and y_local
    float* dS = g_S    + (size_t)b * DD * LL + l0;
    float* dY = g_yloc + (size_t)b * DD * LL + l0;
    for (int j = tid; j < 128 * 128; j += 256) {
        int d = j >> 7, l = j & 127;
        dS[(size_t)d * LL + l] = sA[d * 133 + l];
        dY[(size_t)d * LL + l] = sB[d * 133 + l];
    }
}

// ---------------- K2.5: scan chunk summaries -> h0 per chunk ----------------
__global__ void k25_chainscan(const float* __restrict__ A_log)
{
    int t = blockIdx.x * 256 + threadIdx.x;
    if (t >= BB * DD) return;
    int b = t >> 7, d = t & 127;
    float A1 = -expf(A_log[d * 2 + 0]);
    float A2 = -expf(A_log[d * 2 + 1]);
    float h1 = 0.f, h2 = 0.f;
    for (int c = 0; c < NCH; c++) {
        size_t i = (size_t)(b * NCH + c) * 128 + d;
        g_h0[i * 2 + 0] = h1;
        g_h0[i * 2 + 1] = h2;
        float sd = g_sumdt[i];
        h1 = expf(A1 * sd) * h1 + g_hend[i * 2 + 0];
        h2 = expf(A2 * sd) * h2 + g_hend[i * 2 + 1];
    }
}

// ---------------- K3: finalize y, gate, out-proj GEMM, LayerNorm ----------------
__global__ __launch_bounds__(256) void k3_out(const float* __restrict__ W_out,
                                              const float* __restrict__ A_log,
                                              const float* __restrict__ ln_g,
                                              const float* __restrict__ ln_b,
                                              float* __restrict__ out)
{
    extern __shared__ float sm[];
    float* Ys = sm;                  // [128][132] y tile (d-major) -> reused as O[o][l]
    float* Ws = sm + 128 * 132;      // [128][132] Ws[d][o]
    float* mu = Ws + 128 * 132;      // [128]
    float* rs = mu + 128;            // [128]

    const int tid = threadIdx.x;
    const int b = blockIdx.x >> 5;
    const int c = blockIdx.x & 31;
    const int l0 = c << 7;
    const size_t base = (size_t)b * DD * LL + l0;

    for (int j = tid; j < 128 * 128; j += 256) {
        int d = j >> 7, l = j & 127;
        size_t g = base + (size_t)d * LL + l;
        float yl = g_yloc[g];
        float S  = g_S[g];
        float zv = g_z[g];
        float C1 = g_Cm[((size_t)b * LL + l0 + l) * 2 + 0];
        float C2 = g_Cm[((size_t)b * LL + l0 + l) * 2 + 1];
        size_t hi = (size_t)(b * NCH + c) * 128 + d;
        float h01 = g_h0[hi * 2 + 0], h02 = g_h0[hi * 2 + 1];
        float A1 = -expf(A_log[d * 2 + 0]);
        float A2 = -expf(A_log[d * 2 + 1]);
        float y = yl + C1 * expf(A1 * S) * h01 + C2 * expf(A2 * S) * h02;
        float sg = 1.f / (1.f + expf(-zv));
        Ys[d * 132 + l] = y * (zv * sg);
    }
    for (int j = tid; j < 128 * 128; j += 256) {
        int o = j >> 7, d = j & 127;
        Ws[d * 132 + o] = W_out[o * 128 + d];
    }
    __syncthreads();

    const int tx = tid & 15, ty = tid >> 4;
    float acc[8][8];
#pragma unroll
    for (int jj = 0; jj < 8; jj++)
#pragma unroll
        for (int ii = 0; ii < 8; ii++) acc[jj][ii] = 0.f;

    const float* Ap = Ys + tx * 8;
    const float* Bp = Ws + ty * 8;
#pragma unroll 4
    for (int k = 0; k < 128; k++) {
        float4 a0 = *(const float4*)(Ap + k * 132);
        float4 a1 = *(const float4*)(Ap + k * 132 + 4);
        float4 w0 = *(const float4*)(Bp + k * 132);
        float4 w1 = *(const float4*)(Bp + k * 132 + 4);
        float a[8] = {a0.x, a0.y, a0.z, a0.w, a1.x, a1.y, a1.z, a1.w};
        float w[8] = {w0.x, w0.y, w0.z, w0.w, w1.x, w1.y, w1.z, w1.w};
#pragma unroll
        for (int jj = 0; jj < 8; jj++)
#pragma unroll
            for (int ii = 0; ii < 8; ii++) acc[jj][ii] += w[jj] * a[ii];
    }
    __syncthreads();

    // stage O[o][l] into Ys (dead)
#pragma unroll
    for (int jj = 0; jj < 8; jj++) {
        float4* p = (float4*)&Ys[(ty * 8 + jj) * 132 + tx * 8];
        p[0] = make_float4(acc[jj][0], acc[jj][1], acc[jj][2], acc[jj][3]);
        p[1] = make_float4(acc[jj][4], acc[jj][5], acc[jj][6], acc[jj][7]);
    }
    __syncthreads();

    // LayerNorm stats per token (warp per token)
    {
        int wid = tid >> 5, lane = tid & 31;
        for (int l = wid; l < 128; l += 8) {
            float s = 0.f, s2 = 0.f;
#pragma unroll
            for (int o = lane; o < 128; o += 32) {
                float v = Ys[o * 132 + l];
                s += v; s2 += v * v;
            }
#pragma unroll
            for (int off = 16; off; off >>= 1) {
                s  += __shfl_xor_sync(0xffffffffu, s,  off);
                s2 += __shfl_xor_sync(0xffffffffu, s2, off);
            }
            if (lane == 0) {
                float m = s * (1.f / 128.f);
                mu[l] = m;
                rs[l] = rsqrtf(s2 * (1.f / 128.f) - m * m + 1e-5f);
            }
        }
    }
    __syncthreads();

    float* op = out + base;
    for (int j = tid; j < 128 * 128; j += 256) {
        int o = j >> 7, l = j & 127;
        float v = (Ys[o * 132 + l] - mu[l]) * rs[l] * ln_g[o] + ln_b[o];
        op[(size_t)o * LL + l] = v;
    }
}

// ---------------- launch ----------------
extern "C" void kernel_launch(void* const* d_in, const int* in_sizes, int n_in,
                              void* d_out, int out_size)
{
    const float* x1      = (const float*)d_in[0];
    const float* W_in    = (const float*)d_in[1];
    const float* conv_w  = (const float*)d_in[2];
    const float* conv_b  = (const float*)d_in[3];
    const float* W_xproj = (const float*)d_in[4];
    const float* W_dt    = (const float*)d_in[5];
    const float* b_dt    = (const float*)d_in[6];
    const float* A_log   = (const float*)d_in[7];
    const float* D_param = (const float*)d_in[8];
    const float* W_out   = (const float*)d_in[9];
    const float* ln_g    = (const float*)d_in[10];
    const float* ln_b    = (const float*)d_in[11];
    float* out = (float*)d_out;

    const int smem_k1 = 2 * 128 * 132 * 4;                 // 135168
    const int smem_k2 = (2 * 128 * 133 + 128 * 13 + 512 + 128 + 1536 + 1024 + 128) * 4; // 156160
    const int smem_k3 = (2 * 128 * 132 + 256) * 4;         // 136192

    static bool inited = false;
    if (!inited) {
        cudaFuncSetAttribute(k1_inproj, cudaFuncAttributeMaxDynamicSharedMemorySize, smem_k1);
        cudaFuncSetAttribute(k2_chunk,  cudaFuncAttributeMaxDynamicSharedMemorySize, smem_k2);
        cudaFuncSetAttribute(k3_out,    cudaFuncAttributeMaxDynamicSharedMemorySize, smem_k3);
        inited = true;
    }

    k1_inproj<<<dim3(512, 2), 256, smem_k1>>>(x1, W_in);
    k2_chunk<<<512, 256, smem_k2>>>(conv_w, conv_b, W_xproj, W_dt, b_dt, A_log, D_param);
    k25_chainscan<<<8, 256>>>(A_log);
    k3_out<<<512, 256, smem_k3>>>(W_out, A_log, ln_g, ln_b, out);
}

// round 5
// speedup vs baseline: 1.2164x; 1.2164x over previous
#include <cuda_runtime.h>
#include <cuda_bf16.h>
#include <math.h>
#include <stdint.h>

// Problem constants
#define BB 16
#define DD 128
#define LL 4096
#define NCH 32

// ---------------- scratch ----------------
__device__ float g_xspre[BB * DD * LL];
__device__ float g_z    [BB * DD * LL];
__device__ float g_S    [BB * DD * LL];
__device__ float g_yloc [BB * DD * LL];
__device__ float g_Cm   [BB * LL * 2];
__device__ float g_sumdt[BB * NCH * DD];
__device__ float g_hend [BB * NCH * DD * 2];
__device__ float g_h0   [BB * NCH * DD * 2];

// ---------------- warp MMA helpers (base ISA: sm_80+) ----------------
__device__ __forceinline__ uint32_t smem_u32(const void* p) {
    uint32_t a;
    asm("{ .reg .u64 t; cvta.to.shared.u64 t, %1; cvt.u32.u64 %0, t; }" : "=r"(a) : "l"(p));
    return a;
}
__device__ __forceinline__ void ldsm4(uint32_t addr, uint32_t* r) {
    asm volatile("ldmatrix.sync.aligned.m8n8.x4.shared.b16 {%0,%1,%2,%3}, [%4];"
        : "=r"(r[0]), "=r"(r[1]), "=r"(r[2]), "=r"(r[3]) : "r"(addr));
}
__device__ __forceinline__ void mma_bf16(float* c, const uint32_t* a, uint32_t b0, uint32_t b1) {
    asm volatile("mma.sync.aligned.m16n8k16.row.col.f32.bf16.bf16.f32 "
        "{%0,%1,%2,%3}, {%4,%5,%6,%7}, {%8,%9}, {%0,%1,%2,%3};"
        : "+f"(c[0]), "+f"(c[1]), "+f"(c[2]), "+f"(c[3])
        : "r"(a[0]), "r"(a[1]), "r"(a[2]), "r"(a[3]), "r"(b0), "r"(b1));
}
__device__ __forceinline__ uint32_t pack_bf2(float a, float b) {
    __nv_bfloat16 ha = __float2bfloat16(a), hb = __float2bfloat16(b);
    return (uint32_t)__bfloat16_as_ushort(ha) | ((uint32_t)__bfloat16_as_ushort(hb) << 16);
}
__device__ __forceinline__ void split_pack(float v0, float v1, uint32_t& hi, uint32_t& lo) {
    __nv_bfloat16 h0 = __float2bfloat16(v0), h1 = __float2bfloat16(v1);
    hi = (uint32_t)__bfloat16_as_ushort(h0) | ((uint32_t)__bfloat16_as_ushort(h1) << 16);
    lo = pack_bf2(v0 - __bfloat162float(h0), v1 - __bfloat162float(h1));
}

#define P1 136   // bf16 pitch (272B rows, conflict-free ldmatrix)

// ================= K1: xz = x @ W_in^T  (128 tok x 256 out x K128) =================
#define K1_AHI 1024
#define K1_ALO (K1_AHI + 128 * P1 * 2)
#define K1_BHI (K1_ALO + 128 * P1 * 2)
#define K1_BLO (K1_BHI + 256 * P1 * 2)
#define K1_SMEM (K1_BLO + 256 * P1 * 2)   // 209920

__global__ __launch_bounds__(256) void k1_mma(const float* __restrict__ x1,
                                              const float* __restrict__ W_in)
{
    extern __shared__ char smem[];
    const uint32_t sb = smem_u32(smem);
    const int tid = threadIdx.x, wid = tid >> 5, lane = tid & 31;
    const int b = blockIdx.x >> 5;
    const int l0 = (blockIdx.x & 31) << 7;

    // A tile: x[d][l] -> A[l][d] hi/lo
    const float* xb = x1 + (size_t)b * DD * LL;
    for (int j = tid; j < 64 * 128; j += 256) {
        int dp = j >> 7, l = j & 127, d = dp << 1;
        float v0 = xb[(size_t)d * LL + l0 + l];
        float v1 = xb[(size_t)(d + 1) * LL + l0 + l];
        uint32_t hi, lo; split_pack(v0, v1, hi, lo);
        *(uint32_t*)(smem + K1_AHI + ((size_t)l * P1 + d) * 2) = hi;
        *(uint32_t*)(smem + K1_ALO + ((size_t)l * P1 + d) * 2) = lo;
    }
    // B tile: W_in[e][d] (e = 0..255)
    for (int j = tid; j < 256 * 64; j += 256) {
        int e = j >> 6, dp = j & 63, d = dp << 1;
        float2 w = *(const float2*)(W_in + (size_t)e * 128 + d);
        uint32_t hi, lo; split_pack(w.x, w.y, hi, lo);
        *(uint32_t*)(smem + K1_BHI + ((size_t)e * P1 + d) * 2) = hi;
        *(uint32_t*)(smem + K1_BLO + ((size_t)e * P1 + d) * 2) = lo;
    }
    __syncthreads();

    const int m0 = (wid >> 2) * 64, n0 = (wid & 3) * 64;
    float acc[4][8][4];
#pragma unroll
    for (int mt = 0; mt < 4; mt++)
#pragma unroll
        for (int nt = 0; nt < 8; nt++)
#pragma unroll
            for (int q = 0; q < 4; q++) acc[mt][nt][q] = 0.f;

    const int rsel = lane & 15;
    const int csel = (lane >> 4) * 8;
#pragma unroll
    for (int term = 0; term < 3; term++) {
        uint32_t ab = sb + (term == 2 ? K1_ALO : K1_AHI);
        uint32_t bb = sb + (term == 1 ? K1_BLO : K1_BHI);
#pragma unroll
        for (int ks = 0; ks < 8; ks++) {
            int kc = ks * 16 + csel;
            uint32_t af[4][4], bfr[4][4];
#pragma unroll
            for (int mt = 0; mt < 4; mt++)
                ldsm4(ab + ((uint32_t)(m0 + mt * 16 + rsel) * P1 + kc) * 2, af[mt]);
#pragma unroll
            for (int nt2 = 0; nt2 < 4; nt2++)
                ldsm4(bb + ((uint32_t)(n0 + nt2 * 16 + rsel) * P1 + kc) * 2, bfr[nt2]);
#pragma unroll
            for (int mt = 0; mt < 4; mt++)
#pragma unroll
                for (int nt = 0; nt < 8; nt++)
                    mma_bf16(acc[mt][nt], af[mt],
                             bfr[nt >> 1][nt & 1], bfr[nt >> 1][(nt & 1) + 2]);
        }
    }
    __syncthreads();

    // stage to smem Os[e][132] f32 (reuses tile region), then coalesced store
    float* Os = (float*)(smem + K1_AHI);
    {
        int r = lane >> 2, cc = (lane & 3) * 2;
#pragma unroll
        for (int mt = 0; mt < 4; mt++)
#pragma unroll
            for (int nt = 0; nt < 8; nt++) {
                int l = m0 + mt * 16 + r, e = n0 + nt * 8 + cc;
                Os[e * 132 + l]           = acc[mt][nt][0];
                Os[(e + 1) * 132 + l]     = acc[mt][nt][1];
                Os[e * 132 + l + 8]       = acc[mt][nt][2];
                Os[(e + 1) * 132 + l + 8] = acc[mt][nt][3];
            }
    }
    __syncthreads();
    for (int j = tid; j < 256 * 128; j += 256) {
        int e = j >> 7, l = j & 127;
        float* dst = (e < 128 ? g_xspre : g_z)
                     + (size_t)b * DD * LL + (size_t)(e & 127) * LL + l0 + l;
        *dst = Os[e * 132 + l];
    }
}

// ================= K2: conv+silu, xproj, dt, local scan =================
__global__ __launch_bounds__(256) void k2_chunk(const float* __restrict__ conv_w,
                                                const float* __restrict__ conv_b,
                                                const float* __restrict__ W_xproj,
                                                const float* __restrict__ W_dt,
                                                const float* __restrict__ b_dt,
                                                const float* __restrict__ A_log,
                                                const float* __restrict__ D_param)
{
    extern __shared__ float sm[];
    float* sA    = sm;
    float* sB    = sA + 128 * 133;
    float* sdbl  = sB + 128 * 133;
    float* swc   = sdbl + 128 * 13;
    float* sbc   = swc + 512;
    float* swx   = sbc + 128;
    float* swd   = swx + 1536;
    float* sbd   = swd + 1024;

    const int tid = threadIdx.x;
    const int b = blockIdx.x >> 5;
    const int c = blockIdx.x & 31;
    const int l0 = c << 7;
    const float* src = g_xspre + (size_t)b * DD * LL;

    for (int j = tid; j < 128 * 131; j += 256) {
        int d = j / 131, i = j - d * 131;
        int idx = l0 - 3 + i;
        sA[d * 133 + i] = (idx >= 0) ? src[d * LL + idx] : 0.f;
    }
    for (int j = tid; j < 512; j += 256) swc[j] = conv_w[j];
    if (tid < 128) sbc[tid] = conv_b[tid];
    for (int j = tid; j < 1536; j += 256) swx[j] = W_xproj[j];
    for (int j = tid; j < 1024; j += 256) swd[j] = W_dt[j];
    if (tid < 128) sbd[tid] = b_dt[tid];
    __syncthreads();

    for (int j = tid; j < 128 * 128; j += 256) {
        int d = j >> 7, l = j & 127;
        float v = sbc[d];
        v += swc[d * 4 + 0] * sA[d * 133 + l + 0];
        v += swc[d * 4 + 1] * sA[d * 133 + l + 1];
        v += swc[d * 4 + 2] * sA[d * 133 + l + 2];
        v += swc[d * 4 + 3] * sA[d * 133 + l + 3];
        float sg = 1.f / (1.f + expf(-v));
        sB[d * 133 + l] = v * sg;
    }
    __syncthreads();

    for (int task = tid; task < 12 * 128; task += 256) {
        int jrow = task >> 7, l = task & 127;
        const float* wr = swx + jrow * 128;
        float s = 0.f;
#pragma unroll 8
        for (int d = 0; d < 128; d++) s += sB[d * 133 + l] * wr[d];
        sdbl[l * 13 + jrow] = s;
    }
    __syncthreads();

    for (int j = tid; j < 256; j += 256) {
        int l = j >> 1, n = j & 1;
        g_Cm[((size_t)b * LL + l0 + l) * 2 + n] = sdbl[l * 13 + 10 + n];
    }

    for (int j = tid; j < 128 * 128; j += 256) {
        int d = j >> 7, l = j & 127;
        float v = sbd[d];
        const float* wr = swd + d * 8;
        const float* dr = sdbl + l * 13;
#pragma unroll
        for (int r = 0; r < 8; r++) v += dr[r] * wr[r];
        float sp = (v > 20.f) ? v : log1pf(expf(v));
        sA[d * 133 + l] = sp;
    }
    __syncthreads();

    {
        const int d = tid >> 1, n = tid & 1;
        const float An = -expf(A_log[d * 2 + n]);
        const float Dd = D_param[d];
        float h = 0.f, sd = 0.f;
        for (int l = 0; l < 128; l++) {
            float dtv = sA[d * 133 + l];
            sd += dtv;
            float xv = sB[d * 133 + l];
            float Bn = sdbl[l * 13 + 8 + n];
            float Cn = sdbl[l * 13 + 10 + n];
            h = expf(An * dtv) * h + dtv * Bn * xv;
            float yn = Cn * h;
            float yo = __shfl_xor_sync(0xffffffffu, yn, 1);
            if (n == 0) {
                sB[d * 133 + l] = yn + yo + xv * Dd;
                sA[d * 133 + l] = sd;
            }
        }
        size_t ci = (size_t)(b * NCH + c) * 128 + d;
        if (n == 0) g_sumdt[ci] = sd;
        g_hend[ci * 2 + n] = h;
    }
    __syncthreads();

    float* dS = g_S    + (size_t)b * DD * LL + l0;
    float* dY = g_yloc + (size_t)b * DD * LL + l0;
    for (int j = tid; j < 128 * 128; j += 256) {
        int d = j >> 7, l = j & 127;
        dS[(size_t)d * LL + l] = sA[d * 133 + l];
        dY[(size_t)d * LL + l] = sB[d * 133 + l];
    }
}

// ================= K2.5: chunk-summary scan =================
__global__ void k25_chainscan(const float* __restrict__ A_log)
{
    int t = blockIdx.x * 256 + threadIdx.x;
    if (t >= BB * DD) return;
    int b = t >> 7, d = t & 127;
    float A1 = -expf(A_log[d * 2 + 0]);
    float A2 = -expf(A_log[d * 2 + 1]);
    float h1 = 0.f, h2 = 0.f;
    for (int c = 0; c < NCH; c++) {
        size_t i = (size_t)(b * NCH + c) * 128 + d;
        g_h0[i * 2 + 0] = h1;
        g_h0[i * 2 + 1] = h2;
        float sd = g_sumdt[i];
        h1 = expf(A1 * sd) * h1 + g_hend[i * 2 + 0];
        h2 = expf(A2 * sd) * h2 + g_hend[i * 2 + 1];
    }
}

// ================= K3: finalize y, gate, out-proj, LayerNorm =================
#define K3_EA  0
#define K3_SG  1024
#define K3_SB  1536
#define K3_MU  2048
#define K3_RS  2560
#define K3_AHI 3072
#define K3_ALO (K3_AHI + 128 * P1 * 2)
#define K3_BHI (K3_ALO + 128 * P1 * 2)
#define K3_BLO (K3_BHI + 128 * P1 * 2)
#define K3_SMEM (K3_BLO + 128 * P1 * 2)   // 142336

__global__ __launch_bounds__(256) void k3_mma(const float* __restrict__ W_out,
                                              const float* __restrict__ A_log,
                                              const float* __restrict__ ln_g,
                                              const float* __restrict__ ln_b,
                                              float* __restrict__ out)
{
    extern __shared__ char smem[];
    const uint32_t sb = smem_u32(smem);
    const int tid = threadIdx.x, wid = tid >> 5, lane = tid & 31;
    const int b = blockIdx.x >> 5;
    const int c = blockIdx.x & 31;
    const int l0 = c << 7;
    const size_t base = (size_t)b * DD * LL + l0;

    float* eA  = (float*)(smem + K3_EA);
    float* sg  = (float*)(smem + K3_SG);
    float* sbv = (float*)(smem + K3_SB);
    float* mu  = (float*)(smem + K3_MU);
    float* rs  = (float*)(smem + K3_RS);
    if (tid < 256) eA[tid] = -expf(A_log[tid]);
    if (tid < 128) { sg[tid] = ln_g[tid]; sbv[tid] = ln_b[tid]; }
    __syncthreads();

    // A tile: gated y[l][d] hi/lo
    for (int j = tid; j < 64 * 128; j += 256) {
        int dp = j >> 7, l = j & 127, d = dp << 1;
        float yv[2];
        float2 C = *(const float2*)(g_Cm + ((size_t)b * LL + l0 + l) * 2);
#pragma unroll
        for (int q = 0; q < 2; q++) {
            int dd = d + q;
            size_t g = base + (size_t)dd * LL + l;
            float yl = g_yloc[g];
            float S  = g_S[g];
            float zv = g_z[g];
            size_t hi = (size_t)(b * NCH + c) * 128 + dd;
            float h01 = g_h0[hi * 2 + 0], h02 = g_h0[hi * 2 + 1];
            float A1 = eA[dd * 2 + 0], A2 = eA[dd * 2 + 1];
            float y = yl + C.x * __expf(A1 * S) * h01 + C.y * __expf(A2 * S) * h02;
            float sig = 1.f / (1.f + __expf(-zv));
            yv[q] = y * (zv * sig);
        }
        uint32_t hi32, lo32; split_pack(yv[0], yv[1], hi32, lo32);
        *(uint32_t*)(smem + K3_AHI + ((size_t)l * P1 + d) * 2) = hi32;
        *(uint32_t*)(smem + K3_ALO + ((size_t)l * P1 + d) * 2) = lo32;
    }
    // B tile: W_out[o][d]
    for (int j = tid; j < 128 * 64; j += 256) {
        int o = j >> 6, dp = j & 63, d = dp << 1;
        float2 w = *(const float2*)(W_out + (size_t)o * 128 + d);
        uint32_t hi32, lo32; split_pack(w.x, w.y, hi32, lo32);
        *(uint32_t*)(smem + K3_BHI + ((size_t)o * P1 + d) * 2) = hi32;
        *(uint32_t*)(smem + K3_BLO + ((size_t)o * P1 + d) * 2) = lo32;
    }
    __syncthreads();

    const int m0 = (wid >> 2) * 64, n0 = (wid & 3) * 32;
    float acc[4][4][4];
#pragma unroll
    for (int mt = 0; mt < 4; mt++)
#pragma unroll
        for (int nt = 0; nt < 4; nt++)
#pragma unroll
            for (int q = 0; q < 4; q++) acc[mt][nt][q] = 0.f;

    const int rsel = lane & 15;
    const int csel = (lane >> 4) * 8;
#pragma unroll
    for (int term = 0; term < 3; term++) {
        uint32_t ab = sb + (term == 2 ? K3_ALO : K3_AHI);
        uint32_t bb = sb + (term == 1 ? K3_BLO : K3_BHI);
#pragma unroll
        for (int ks = 0; ks < 8; ks++) {
            int kc = ks * 16 + csel;
            uint32_t af[4][4], bfr[2][4];
#pragma unroll
            for (int mt = 0; mt < 4; mt++)
                ldsm4(ab + ((uint32_t)(m0 + mt * 16 + rsel) * P1 + kc) * 2, af[mt]);
#pragma unroll
            for (int nt2 = 0; nt2 < 2; nt2++)
                ldsm4(bb + ((uint32_t)(n0 + nt2 * 16 + rsel) * P1 + kc) * 2, bfr[nt2]);
#pragma unroll
            for (int mt = 0; mt < 4; mt++)
#pragma unroll
                for (int nt = 0; nt < 4; nt++)
                    mma_bf16(acc[mt][nt], af[mt],
                             bfr[nt >> 1][nt & 1], bfr[nt >> 1][(nt & 1) + 2]);
        }
    }
    __syncthreads();

    // stage O[o][132] f32 (reuses A tile region)
    float* Os = (float*)(smem + K3_AHI);
    {
        int r = lane >> 2, cc = (lane & 3) * 2;
#pragma unroll
        for (int mt = 0; mt < 4; mt++)
#pragma unroll
            for (int nt = 0; nt < 4; nt++) {
                int l = m0 + mt * 16 + r, o = n0 + nt * 8 + cc;
                Os[o * 132 + l]           = acc[mt][nt][0];
                Os[(o + 1) * 132 + l]     = acc[mt][nt][1];
                Os[o * 132 + l + 8]       = acc[mt][nt][2];
                Os[(o + 1) * 132 + l + 8] = acc[mt][nt][3];
            }
    }
    __syncthreads();

    // LayerNorm stats: warp per token
    for (int l = wid; l < 128; l += 8) {
        float s = 0.f, s2 = 0.f;
#pragma unroll
        for (int o = lane; o < 128; o += 32) {
            float v = Os[o * 132 + l];
            s += v; s2 += v * v;
        }
#pragma unroll
        for (int off = 16; off; off >>= 1) {
            s  += __shfl_xor_sync(0xffffffffu, s,  off);
            s2 += __shfl_xor_sync(0xffffffffu, s2, off);
        }
        if (lane == 0) {
            float m = s * (1.f / 128.f);
            mu[l] = m;
            rs[l] = rsqrtf(s2 * (1.f / 128.f) - m * m + 1e-5f);
        }
    }
    __syncthreads();

    float* op = out + base;
    for (int j = tid; j < 128 * 128; j += 256) {
        int o = j >> 7, l = j & 127;
        float v = (Os[o * 132 + l] - mu[l]) * rs[l] * sg[o] + sbv[o];
        op[(size_t)o * LL + l] = v;
    }
}

// ---------------- launch ----------------
extern "C" void kernel_launch(void* const* d_in, const int* in_sizes, int n_in,
                              void* d_out, int out_size)
{
    const float* x1      = (const float*)d_in[0];
    const float* W_in    = (const float*)d_in[1];
    const float* conv_w  = (const float*)d_in[2];
    const float* conv_b  = (const float*)d_in[3];
    const float* W_xproj = (const float*)d_in[4];
    const float* W_dt    = (const float*)d_in[5];
    const float* b_dt    = (const float*)d_in[6];
    const float* A_log   = (const float*)d_in[7];
    const float* D_param = (const float*)d_in[8];
    const float* W_out   = (const float*)d_in[9];
    const float* ln_g    = (const float*)d_in[10];
    const float* ln_b    = (const float*)d_in[11];
    float* out = (float*)d_out;

    const int smem_k2 = (2 * 128 * 133 + 128 * 13 + 512 + 128 + 1536 + 1024 + 128) * 4;

    static bool inited = false;
    if (!inited) {
        cudaFuncSetAttribute(k1_mma, cudaFuncAttributeMaxDynamicSharedMemorySize, K1_SMEM);
        cudaFuncSetAttribute(k2_chunk, cudaFuncAttributeMaxDynamicSharedMemorySize, smem_k2);
        cudaFuncSetAttribute(k3_mma, cudaFuncAttributeMaxDynamicSharedMemorySize, K3_SMEM);
        inited = true;
    }

    k1_mma<<<512, 256, K1_SMEM>>>(x1, W_in);
    k2_chunk<<<512, 256, smem_k2>>>(conv_w, conv_b, W_xproj, W_dt, b_dt, A_log, D_param);
    k25_chainscan<<<8, 256>>>(A_log);
    k3_mma<<<512, 256, K3_SMEM>>>(W_out, A_log, ln_g, ln_b, out);
}

// round 6
// speedup vs baseline: 1.3381x; 1.1001x over previous
#include <cuda_runtime.h>
#include <cuda_bf16.h>
#include <math.h>
#include <stdint.h>

// Problem constants
#define BB 16
#define DD 128
#define LL 4096
#define CL 64
#define NCH 64          // chunks per batch (LL/CL)

// ---------------- scratch ----------------
__device__ float g_xspre[BB * DD * LL];
__device__ float g_z    [BB * DD * LL];
__device__ float g_S    [BB * DD * LL];
__device__ float g_yloc [BB * DD * LL];
__device__ float g_Cm   [BB * LL * 2];
__device__ float g_sumdt[BB * NCH * DD];
__device__ float g_hend [BB * NCH * DD * 2];
__device__ float g_h0   [BB * NCH * DD * 2];

// ---------------- helpers ----------------
__device__ __forceinline__ uint32_t smem_u32(const void* p) {
    uint32_t a;
    asm("{ .reg .u64 t; cvta.to.shared.u64 t, %1; cvt.u32.u64 %0, t; }" : "=r"(a) : "l"(p));
    return a;
}
__device__ __forceinline__ void ldsm4(uint32_t addr, uint32_t* r) {
    asm volatile("ldmatrix.sync.aligned.m8n8.x4.shared.b16 {%0,%1,%2,%3}, [%4];"
        : "=r"(r[0]), "=r"(r[1]), "=r"(r[2]), "=r"(r[3]) : "r"(addr));
}
__device__ __forceinline__ void mma_bf16(float* c, const uint32_t* a, uint32_t b0, uint32_t b1) {
    asm volatile("mma.sync.aligned.m16n8k16.row.col.f32.bf16.bf16.f32 "
        "{%0,%1,%2,%3}, {%4,%5,%6,%7}, {%8,%9}, {%0,%1,%2,%3};"
        : "+f"(c[0]), "+f"(c[1]), "+f"(c[2]), "+f"(c[3])
        : "r"(a[0]), "r"(a[1]), "r"(a[2]), "r"(a[3]), "r"(b0), "r"(b1));
}
__device__ __forceinline__ uint32_t pack_bf2(float a, float b) {
    __nv_bfloat16 ha = __float2bfloat16(a), hb = __float2bfloat16(b);
    return (uint32_t)__bfloat16_as_ushort(ha) | ((uint32_t)__bfloat16_as_ushort(hb) << 16);
}
__device__ __forceinline__ void split_pack(float v0, float v1, uint32_t& hi, uint32_t& lo) {
    __nv_bfloat16 h0 = __float2bfloat16(v0), h1 = __float2bfloat16(v1);
    hi = (uint32_t)__bfloat16_as_ushort(h0) | ((uint32_t)__bfloat16_as_ushort(h1) << 16);
    lo = pack_bf2(v0 - __bfloat162float(h0), v1 - __bfloat162float(h1));
}
// 128B-row tile (128 rows x 64 bf16 cols), XOR swizzle -> conflict-free ldmatrix
#define SWZ(o) ((o) ^ ((((o) >> 7) & 7) << 4))

// ================= K1: xz = x @ W_in^T =================
// grid (512, 2): 128 tokens x 128 outputs, K-split staging of 64 cols
#define K1_TAH 0
#define K1_TAL 16384
#define K1_TBH 32768
#define K1_TBL 49152
#define K1_SMEM 65536

__global__ __launch_bounds__(256, 2) void k1_mma(const float* __restrict__ x1,
                                                 const float* __restrict__ W_in)
{
    extern __shared__ char smem[];
    const uint32_t sb = smem_u32(smem);
    const int tid = threadIdx.x, wid = tid >> 5, lane = tid & 31;
    const int b = blockIdx.x >> 5;
    const int l0 = (blockIdx.x & 31) << 7;
    const int ebase = blockIdx.y << 7;

    const int m0 = (wid >> 2) * 64, n0 = (wid & 3) * 32;
    const int rsel = lane & 15;
    const int csel = (lane >> 4) * 8;

    float acc[4][4][4];
#pragma unroll
    for (int mt = 0; mt < 4; mt++)
#pragma unroll
        for (int nt = 0; nt < 4; nt++)
#pragma unroll
            for (int q = 0; q < 4; q++) acc[mt][nt][q] = 0.f;

    const float* xb = x1 + (size_t)b * DD * LL;

#pragma unroll 1
    for (int h = 0; h < 2; h++) {
        const int d0 = h << 6;
        if (h) __syncthreads();
        // stage A half: rows = token l, cols = d-d0 (bf16 pairs)
#pragma unroll 4
        for (int j = tid; j < 4096; j += 256) {
            int l = j & 127, dp = j >> 7, d = d0 + dp * 2;
            float v0 = xb[(size_t)d * LL + l0 + l];
            float v1 = xb[(size_t)(d + 1) * LL + l0 + l];
            uint32_t hi, lo; split_pack(v0, v1, hi, lo);
            uint32_t off = SWZ((uint32_t)l * 128u + (uint32_t)dp * 4u);
            *(uint32_t*)(smem + K1_TAH + off) = hi;
            *(uint32_t*)(smem + K1_TAL + off) = lo;
        }
        // stage B half: rows = e-local, cols = d-d0
#pragma unroll 4
        for (int j = tid; j < 4096; j += 256) {
            int eL = j >> 5, dp = j & 31, d = d0 + dp * 2;
            float2 w = *(const float2*)(W_in + (size_t)(ebase + eL) * 128 + d);
            uint32_t hi, lo; split_pack(w.x, w.y, hi, lo);
            uint32_t off = SWZ((uint32_t)eL * 128u + (uint32_t)dp * 4u);
            *(uint32_t*)(smem + K1_TBH + off) = hi;
            *(uint32_t*)(smem + K1_TBL + off) = lo;
        }
        __syncthreads();

#pragma unroll 1
        for (int term = 0; term < 3; term++) {
            uint32_t ab = sb + (term == 2 ? K1_TAL : K1_TAH);
            uint32_t bb = sb + (term == 1 ? K1_TBL : K1_TBH);
#pragma unroll
            for (int ks = 0; ks < 4; ks++) {
                uint32_t kc = (uint32_t)(ks * 16 + csel) * 2u;
                uint32_t af[4][4], bfr[2][4];
#pragma unroll
                for (int mt = 0; mt < 4; mt++)
                    ldsm4(ab + SWZ((uint32_t)(m0 + mt * 16 + rsel) * 128u + kc), af[mt]);
#pragma unroll
                for (int nt2 = 0; nt2 < 2; nt2++)
                    ldsm4(bb + SWZ((uint32_t)(n0 + nt2 * 16 + rsel) * 128u + kc), bfr[nt2]);
#pragma unroll
                for (int mt = 0; mt < 4; mt++)
#pragma unroll
                    for (int nt = 0; nt < 4; nt++)
                        mma_bf16(acc[mt][nt], af[mt],
                                 bfr[nt >> 1][nt & 1], bfr[nt >> 1][(nt & 1) + 2]);
            }
        }
    }

    // direct fragment store (full 32B sectors)
    {
        int r = lane >> 2, cc = (lane & 3) * 2;
        float* dst = (blockIdx.y ? g_z : g_xspre) + (size_t)b * DD * LL + l0;
#pragma unroll
        for (int mt = 0; mt < 4; mt++)
#pragma unroll
            for (int nt = 0; nt < 4; nt++) {
                int l = m0 + mt * 16 + r;
                int e = n0 + nt * 8 + cc;
                dst[(size_t)e * LL + l]           = acc[mt][nt][0];
                dst[(size_t)(e + 1) * LL + l]     = acc[mt][nt][1];
                dst[(size_t)e * LL + l + 8]       = acc[mt][nt][2];
                dst[(size_t)(e + 1) * LL + l + 8] = acc[mt][nt][3];
            }
    }
}

// ================= K2: conv+silu, xproj, dt, local scan (64-token chunks) =================
#define PC 69
__global__ __launch_bounds__(256, 2) void k2_chunk(const float* __restrict__ conv_w,
                                                   const float* __restrict__ conv_b,
                                                   const float* __restrict__ W_xproj,
                                                   const float* __restrict__ W_dt,
                                                   const float* __restrict__ b_dt,
                                                   const float* __restrict__ A_log,
                                                   const float* __restrict__ D_param)
{
    extern __shared__ float sm[];
    float* sA    = sm;                      // [128][PC]
    float* sB    = sA + 128 * PC;           // [128][PC]
    float* sdbl  = sB + 128 * PC;           // [64][13]
    float* swc   = sdbl + 64 * 13;
    float* sbc   = swc + 512;
    float* swx   = sbc + 128;
    float* swd   = swx + 1536;
    float* sbd   = swd + 1024;

    const int tid = threadIdx.x;
    const int b = blockIdx.x >> 6;
    const int c = blockIdx.x & 63;
    const int l0 = c << 6;
    const float* src = g_xspre + (size_t)b * DD * LL;

    for (int j = tid; j < 128 * 67; j += 256) {
        int d = j / 67, i = j - d * 67;
        int idx = l0 - 3 + i;
        sA[d * PC + i] = (idx >= 0) ? src[(size_t)d * LL + idx] : 0.f;
    }
    for (int j = tid; j < 512; j += 256) swc[j] = conv_w[j];
    if (tid < 128) sbc[tid] = conv_b[tid];
    for (int j = tid; j < 1536; j += 256) swx[j] = W_xproj[j];
    for (int j = tid; j < 1024; j += 256) swd[j] = W_dt[j];
    if (tid < 128) sbd[tid] = b_dt[tid];
    __syncthreads();

    // depthwise conv + silu -> sB
    for (int j = tid; j < 128 * 64; j += 256) {
        int d = j >> 6, l = j & 63;
        float v = sbc[d];
        v += swc[d * 4 + 0] * sA[d * PC + l + 0];
        v += swc[d * 4 + 1] * sA[d * PC + l + 1];
        v += swc[d * 4 + 2] * sA[d * PC + l + 2];
        v += swc[d * 4 + 3] * sA[d * PC + l + 3];
        float sg = 1.f / (1.f + expf(-v));
        sB[d * PC + l] = v * sg;
    }
    __syncthreads();

    // xproj: dbl[l][j]
    for (int task = tid; task < 12 * 64; task += 256) {
        int jrow = task >> 6, l = task & 63;
        const float* wr = swx + jrow * 128;
        float s = 0.f;
#pragma unroll 8
        for (int d = 0; d < 128; d++) s += sB[d * PC + l] * wr[d];
        sdbl[l * 13 + jrow] = s;
    }
    __syncthreads();

    if (tid < 128) {
        int l = tid >> 1, n = tid & 1;
        g_Cm[((size_t)b * LL + l0 + l) * 2 + n] = sdbl[l * 13 + 10 + n];
    }

    // dt -> sA
    for (int j = tid; j < 128 * 64; j += 256) {
        int d = j >> 6, l = j & 63;
        float v = sbd[d];
        const float* wr = swd + d * 8;
        const float* dr = sdbl + l * 13;
#pragma unroll
        for (int r = 0; r < 8; r++) v += dr[r] * wr[r];
        float sp = (v > 20.f) ? v : log1pf(expf(v));
        sA[d * PC + l] = sp;
    }
    __syncthreads();

    // local scan
    {
        const int d = tid >> 1, n = tid & 1;
        const float An = -expf(A_log[d * 2 + n]);
        const float Dd = D_param[d];
        float h = 0.f, sd = 0.f;
        for (int l = 0; l < 64; l++) {
            float dtv = sA[d * PC + l];
            sd += dtv;
            float xv = sB[d * PC + l];
            float Bn = sdbl[l * 13 + 8 + n];
            float Cn = sdbl[l * 13 + 10 + n];
            h = expf(An * dtv) * h + dtv * Bn * xv;
            float yn = Cn * h;
            float yo = __shfl_xor_sync(0xffffffffu, yn, 1);
            if (n == 0) {
                sB[d * PC + l] = yn + yo + xv * Dd;
                sA[d * PC + l] = sd;
            }
        }
        size_t ci = (size_t)(b * NCH + c) * 128 + d;
        if (n == 0) g_sumdt[ci] = sd;
        g_hend[ci * 2 + n] = h;
    }
    __syncthreads();

    float* dS = g_S    + (size_t)b * DD * LL + l0;
    float* dY = g_yloc + (size_t)b * DD * LL + l0;
    for (int j = tid; j < 128 * 64; j += 256) {
        int d = j >> 6, l = j & 63;
        dS[(size_t)d * LL + l] = sA[d * PC + l];
        dY[(size_t)d * LL + l] = sB[d * PC + l];
    }
}

// ================= K2.5: chunk-summary scan =================
__global__ void k25_chainscan(const float* __restrict__ A_log)
{
    int t = blockIdx.x * 256 + threadIdx.x;
    if (t >= BB * DD) return;
    int b = t >> 7, d = t & 127;
    float A1 = -expf(A_log[d * 2 + 0]);
    float A2 = -expf(A_log[d * 2 + 1]);
    float h1 = 0.f, h2 = 0.f;
    for (int c = 0; c < NCH; c++) {
        size_t i = (size_t)(b * NCH + c) * 128 + d;
        g_h0[i * 2 + 0] = h1;
        g_h0[i * 2 + 1] = h2;
        float sd = g_sumdt[i];
        h1 = expf(A1 * sd) * h1 + g_hend[i * 2 + 0];
        h2 = expf(A2 * sd) * h2 + g_hend[i * 2 + 1];
    }
}

// ================= K3: finalize y, gate, out-proj, LayerNorm =================
#define K3_TAH 0
#define K3_TAL 16384
#define K3_TBH 32768
#define K3_TBL 49152
#define K3_EA  67584
#define K3_SG  68608
#define K3_SBv 69120
#define K3_MU  69632
#define K3_RS  70144
#define K3_SMEM 70656

__global__ __launch_bounds__(256, 2) void k3_mma(const float* __restrict__ W_out,
                                                 const float* __restrict__ A_log,
                                                 const float* __restrict__ ln_g,
                                                 const float* __restrict__ ln_b,
                                                 float* __restrict__ out)
{
    extern __shared__ char smem[];
    const uint32_t sb = smem_u32(smem);
    const int tid = threadIdx.x, wid = tid >> 5, lane = tid & 31;
    const int b = blockIdx.x >> 5;
    const int l0 = (blockIdx.x & 31) << 7;
    const size_t base = (size_t)b * DD * LL + l0;

    float* eA  = (float*)(smem + K3_EA);
    float* sg  = (float*)(smem + K3_SG);
    float* sbv = (float*)(smem + K3_SBv);
    float* mu  = (float*)(smem + K3_MU);
    float* rs  = (float*)(smem + K3_RS);
    if (tid < 256) eA[tid] = -expf(A_log[tid]);
    if (tid < 128) { sg[tid] = ln_g[tid]; sbv[tid] = ln_b[tid]; }
    __syncthreads();

    const int m0 = (wid >> 2) * 64, n0 = (wid & 3) * 32;
    const int rsel = lane & 15;
    const int csel = (lane >> 4) * 8;

    float acc[4][4][4];
#pragma unroll
    for (int mt = 0; mt < 4; mt++)
#pragma unroll
        for (int nt = 0; nt < 4; nt++)
#pragma unroll
            for (int q = 0; q < 4; q++) acc[mt][nt][q] = 0.f;

#pragma unroll 1
    for (int h = 0; h < 2; h++) {
        const int d0 = h << 6;
        if (h) __syncthreads();
        // stage A half: gated y[l][d]
#pragma unroll 2
        for (int j = tid; j < 4096; j += 256) {
            int l = j & 127, dp = j >> 7, d = d0 + dp * 2;
            int c64 = (l0 + l) >> 6;
            float2 C = *(const float2*)(g_Cm + ((size_t)b * LL + l0 + l) * 2);
            float yv[2];
#pragma unroll
            for (int q = 0; q < 2; q++) {
                int dd = d + q;
                size_t g = base + (size_t)dd * LL + l;
                float yl = g_yloc[g];
                float S  = g_S[g];
                float zv = g_z[g];
                size_t hi = (size_t)(b * NCH + c64) * 128 + dd;
                float h01 = g_h0[hi * 2 + 0], h02 = g_h0[hi * 2 + 1];
                float A1 = eA[dd * 2 + 0], A2 = eA[dd * 2 + 1];
                float y = yl + C.x * __expf(A1 * S) * h01 + C.y * __expf(A2 * S) * h02;
                float sig = 1.f / (1.f + __expf(-zv));
                yv[q] = y * (zv * sig);
            }
            uint32_t hi32, lo32; split_pack(yv[0], yv[1], hi32, lo32);
            uint32_t off = SWZ((uint32_t)l * 128u + (uint32_t)dp * 4u);
            *(uint32_t*)(smem + K3_TAH + off) = hi32;
            *(uint32_t*)(smem + K3_TAL + off) = lo32;
        }
        // stage B half: W_out[o][d]
#pragma unroll 4
        for (int j = tid; j < 4096; j += 256) {
            int o = j >> 5, dp = j & 31, d = d0 + dp * 2;
            float2 w = *(const float2*)(W_out + (size_t)o * 128 + d);
            uint32_t hi32, lo32; split_pack(w.x, w.y, hi32, lo32);
            uint32_t off = SWZ((uint32_t)o * 128u + (uint32_t)dp * 4u);
            *(uint32_t*)(smem + K3_TBH + off) = hi32;
            *(uint32_t*)(smem + K3_TBL + off) = lo32;
        }
        __syncthreads();

#pragma unroll 1
        for (int term = 0; term < 3; term++) {
            uint32_t ab = sb + (term == 2 ? K3_TAL : K3_TAH);
            uint32_t bb = sb + (term == 1 ? K3_TBL : K3_TBH);
#pragma unroll
            for (int ks = 0; ks < 4; ks++) {
                uint32_t kc = (uint32_t)(ks * 16 + csel) * 2u;
                uint32_t af[4][4], bfr[2][4];
#pragma unroll
                for (int mt = 0; mt < 4; mt++)
                    ldsm4(ab + SWZ((uint32_t)(m0 + mt * 16 + rsel) * 128u + kc), af[mt]);
#pragma unroll
                for (int nt2 = 0; nt2 < 2; nt2++)
                    ldsm4(bb + SWZ((uint32_t)(n0 + nt2 * 16 + rsel) * 128u + kc), bfr[nt2]);
#pragma unroll
                for (int mt = 0; mt < 4; mt++)
#pragma unroll
                    for (int nt = 0; nt < 4; nt++)
                        mma_bf16(acc[mt][nt], af[mt],
                                 bfr[nt >> 1][nt & 1], bfr[nt >> 1][(nt & 1) + 2]);
            }
        }
    }
    __syncthreads();

    // stage O[o][132] f32 (overlays tiles)
    float* Os = (float*)smem;
    {
        int r = lane >> 2, cc = (lane & 3) * 2;
#pragma unroll
        for (int mt = 0; mt < 4; mt++)
#pragma unroll
            for (int nt = 0; nt < 4; nt++) {
                int l = m0 + mt * 16 + r, o = n0 + nt * 8 + cc;
                Os[o * 132 + l]           = acc[mt][nt][0];
                Os[(o + 1) * 132 + l]     = acc[mt][nt][1];
                Os[o * 132 + l + 8]       = acc[mt][nt][2];
                Os[(o + 1) * 132 + l + 8] = acc[mt][nt][3];
            }
    }
    __syncthreads();

    // LayerNorm stats: warp per token
    for (int l = wid; l < 128; l += 8) {
        float s = 0.f, s2 = 0.f;
#pragma unroll
        for (int o = lane; o < 128; o += 32) {
            float v = Os[o * 132 + l];
            s += v; s2 += v * v;
        }
#pragma unroll
        for (int off = 16; off; off >>= 1) {
            s  += __shfl_xor_sync(0xffffffffu, s,  off);
            s2 += __shfl_xor_sync(0xffffffffu, s2, off);
        }
        if (lane == 0) {
            float m = s * (1.f / 128.f);
            mu[l] = m;
            rs[l] = rsqrtf(s2 * (1.f / 128.f) - m * m + 1e-5f);
        }
    }
    __syncthreads();

    float* op = out + base;
    for (int j = tid; j < 128 * 128; j += 256) {
        int o = j >> 7, l = j & 127;
        float v = (Os[o * 132 + l] - mu[l]) * rs[l] * sg[o] + sbv[o];
        op[(size_t)o * LL + l] = v;
    }
}

// ---------------- launch ----------------
extern "C" void kernel_launch(void* const* d_in, const int* in_sizes, int n_in,
                              void* d_out, int out_size)
{
    const float* x1      = (const float*)d_in[0];
    const float* W_in    = (const float*)d_in[1];
    const float* conv_w  = (const float*)d_in[2];
    const float* conv_b  = (const float*)d_in[3];
    const float* W_xproj = (const float*)d_in[4];
    const float* W_dt    = (const float*)d_in[5];
    const float* b_dt    = (const float*)d_in[6];
    const float* A_log   = (const float*)d_in[7];
    const float* D_param = (const float*)d_in[8];
    const float* W_out   = (const float*)d_in[9];
    const float* ln_g    = (const float*)d_in[10];
    const float* ln_b    = (const float*)d_in[11];
    float* out = (float*)d_out;

    const int smem_k2 = (2 * 128 * PC + 64 * 13 + 512 + 128 + 1536 + 1024 + 128) * 4;

    static bool inited = false;
    if (!inited) {
        cudaFuncSetAttribute(k1_mma, cudaFuncAttributeMaxDynamicSharedMemorySize, K1_SMEM);
        cudaFuncSetAttribute(k2_chunk, cudaFuncAttributeMaxDynamicSharedMemorySize, smem_k2);
        cudaFuncSetAttribute(k3_mma, cudaFuncAttributeMaxDynamicSharedMemorySize, K3_SMEM);
        inited = true;
    }

    k1_mma<<<dim3(512, 2), 256, K1_SMEM>>>(x1, W_in);
    k2_chunk<<<1024, 256, smem_k2>>>(conv_w, conv_b, W_xproj, W_dt, b_dt, A_log, D_param);
    k25_chainscan<<<8, 256>>>(A_log);
    k3_mma<<<512, 256, K3_SMEM>>>(W_out, A_log, ln_g, ln_b, out);
}

// round 8
// speedup vs baseline: 1.8248x; 1.3637x over previous
#include <cuda_runtime.h>
#include <cuda_bf16.h>
#include <math.h>
#include <stdint.h>

// Problem constants
#define BB 16
#define DD 128
#define LL 4096
#define NCH 64          // 64-token chunks per batch

// ---------------- scratch ----------------
__device__ float g_xspre[BB * DD * LL];
__device__ float g_z    [BB * DD * LL];
__device__ float g_S    [BB * DD * LL];
__device__ float g_yloc [BB * DD * LL];
__device__ float g_Cm   [BB * LL * 2];
__device__ float g_sumdt[BB * NCH * DD];
__device__ float g_hend [BB * NCH * DD * 2];
__device__ float g_h0   [BB * NCH * DD * 2];

// ---------------- helpers ----------------
__device__ __forceinline__ uint32_t smem_u32(const void* p) {
    uint32_t a;
    asm("{ .reg .u64 t; cvta.to.shared.u64 t, %1; cvt.u32.u64 %0, t; }" : "=r"(a) : "l"(p));
    return a;
}
__device__ __forceinline__ void ldsm4(uint32_t addr, uint32_t* r) {
    asm volatile("ldmatrix.sync.aligned.m8n8.x4.shared.b16 {%0,%1,%2,%3}, [%4];"
        : "=r"(r[0]), "=r"(r[1]), "=r"(r[2]), "=r"(r[3]) : "r"(addr));
}
__device__ __forceinline__ void mma_bf16(float* c, const uint32_t* a, uint32_t b0, uint32_t b1) {
    asm volatile("mma.sync.aligned.m16n8k16.row.col.f32.bf16.bf16.f32 "
        "{%0,%1,%2,%3}, {%4,%5,%6,%7}, {%8,%9}, {%0,%1,%2,%3};"
        : "+f"(c[0]), "+f"(c[1]), "+f"(c[2]), "+f"(c[3])
        : "r"(a[0]), "r"(a[1]), "r"(a[2]), "r"(a[3]), "r"(b0), "r"(b1));
}
__device__ __forceinline__ uint32_t pack_bf2(float a, float b) {
    __nv_bfloat16 ha = __float2bfloat16(a), hb = __float2bfloat16(b);
    return (uint32_t)__bfloat16_as_ushort(ha) | ((uint32_t)__bfloat16_as_ushort(hb) << 16);
}
__device__ __forceinline__ void split_pack(float v0, float v1, uint32_t& hi, uint32_t& lo) {
    __nv_bfloat16 h0 = __float2bfloat16(v0), h1 = __float2bfloat16(v1);
    hi = (uint32_t)__bfloat16_as_ushort(h0) | ((uint32_t)__bfloat16_as_ushort(h1) << 16);
    lo = pack_bf2(v0 - __bfloat162float(h0), v1 - __bfloat162float(h1));
}
// 128B-row tiles, XOR swizzle -> conflict-free ldmatrix
#define SWZ(o) ((o) ^ ((((o) >> 7) & 7) << 4))

// ================= K1: xz = x @ W_in^T =================
// grid (1024, 2): 64 tokens x 128 outputs per block, 128 threads, 4 CTAs/SM
#define K1_TAH 0
#define K1_TAL 8192
#define K1_TBH 16384
#define K1_TBL 32768
#define K1_SMEM 49152

__global__ __launch_bounds__(128, 4) void k1_mma(const float* __restrict__ x1,
                                                 const float* __restrict__ W_in)
{
    extern __shared__ char smem[];
    const uint32_t sb = smem_u32(smem);
    const int tid = threadIdx.x, wid = tid >> 5, lane = tid & 31;
    const int b = blockIdx.x >> 6;
    const int l0 = (blockIdx.x & 63) << 6;
    const int ebase = blockIdx.y << 7;

    const int m0 = (wid & 1) * 32, n0 = (wid >> 1) * 64;
    const int rsel = lane & 15;
    const int csel = (lane >> 4) * 8;

    float acc[2][8][4];
#pragma unroll
    for (int mt = 0; mt < 2; mt++)
#pragma unroll
        for (int nt = 0; nt < 8; nt++)
#pragma unroll
            for (int q = 0; q < 4; q++) acc[mt][nt][q] = 0.f;

    const float* xb = x1 + (size_t)b * DD * LL;

#pragma unroll 1
    for (int h = 0; h < 2; h++) {
        const int d0 = h << 6;
        if (h) __syncthreads();
        // stage A half: rows = token l (64), cols = 32 bf16-pairs
#pragma unroll 4
        for (int j = tid; j < 2048; j += 128) {
            int l = j & 63, dp = j >> 6, d = d0 + dp * 2;
            float v0 = xb[(size_t)d * LL + l0 + l];
            float v1 = xb[(size_t)(d + 1) * LL + l0 + l];
            uint32_t hi, lo; split_pack(v0, v1, hi, lo);
            uint32_t off = SWZ((uint32_t)l * 128u + (uint32_t)dp * 4u);
            *(uint32_t*)(smem + K1_TAH + off) = hi;
            *(uint32_t*)(smem + K1_TAL + off) = lo;
        }
        // stage B half: rows = e-local (128)
#pragma unroll 4
        for (int j = tid; j < 4096; j += 128) {
            int eL = j >> 5, dp = j & 31, d = d0 + dp * 2;
            float2 w = *(const float2*)(W_in + (size_t)(ebase + eL) * 128 + d);
            uint32_t hi, lo; split_pack(w.x, w.y, hi, lo);
            uint32_t off = SWZ((uint32_t)eL * 128u + (uint32_t)dp * 4u);
            *(uint32_t*)(smem + K1_TBH + off) = hi;
            *(uint32_t*)(smem + K1_TBL + off) = lo;
        }
        __syncthreads();

#pragma unroll 1
        for (int term = 0; term < 3; term++) {
            uint32_t ab = sb + (term == 2 ? K1_TAL : K1_TAH);
            uint32_t bb = sb + (term == 1 ? K1_TBL : K1_TBH);
#pragma unroll
            for (int ks = 0; ks < 4; ks++) {
                uint32_t kc = (uint32_t)(ks * 16 + csel) * 2u;
                uint32_t af[2][4], bfr[4][4];
#pragma unroll
                for (int mt = 0; mt < 2; mt++)
                    ldsm4(ab + SWZ((uint32_t)(m0 + mt * 16 + rsel) * 128u + kc), af[mt]);
#pragma unroll
                for (int nt2 = 0; nt2 < 4; nt2++)
                    ldsm4(bb + SWZ((uint32_t)(n0 + nt2 * 16 + rsel) * 128u + kc), bfr[nt2]);
#pragma unroll
                for (int mt = 0; mt < 2; mt++)
#pragma unroll
                    for (int nt = 0; nt < 8; nt++)
                        mma_bf16(acc[mt][nt], af[mt],
                                 bfr[nt >> 1][nt & 1], bfr[nt >> 1][(nt & 1) + 2]);
            }
        }
    }

    // direct fragment store
    {
        int r = lane >> 2, cc = (lane & 3) * 2;
        float* dst = (blockIdx.y ? g_z : g_xspre) + (size_t)b * DD * LL + l0;
#pragma unroll
        for (int mt = 0; mt < 2; mt++)
#pragma unroll
            for (int nt = 0; nt < 8; nt++) {
                int l = m0 + mt * 16 + r;
                int e = n0 + nt * 8 + cc;
                dst[(size_t)e * LL + l]           = acc[mt][nt][0];
                dst[(size_t)(e + 1) * LL + l]     = acc[mt][nt][1];
                dst[(size_t)e * LL + l + 8]       = acc[mt][nt][2];
                dst[(size_t)(e + 1) * LL + l + 8] = acc[mt][nt][3];
            }
    }
}

// ================= K2: conv+silu, xproj, dt, local scan (64-token chunks) =================
#define PC 69
__global__ __launch_bounds__(256, 3) void k2_chunk(const float* __restrict__ conv_w,
                                                   const float* __restrict__ conv_b,
                                                   const float* __restrict__ W_xproj,
                                                   const float* __restrict__ W_dt,
                                                   const float* __restrict__ b_dt,
                                                   const float* __restrict__ A_log,
                                                   const float* __restrict__ D_param)
{
    extern __shared__ float sm[];
    float* sA    = sm;                      // [128][PC]
    float* sB    = sA + 128 * PC;           // [128][PC]
    float* sdbl  = sB + 128 * PC;           // [64][13]
    float* swc   = sdbl + 64 * 13;
    float* sbc   = swc + 512;
    float* swx   = sbc + 128;
    float* swd   = swx + 1536;
    float* sbd   = swd + 1024;

    const int tid = threadIdx.x;
    const int b = blockIdx.x >> 6;
    const int c = blockIdx.x & 63;
    const int l0 = c << 6;
    const float* src = g_xspre + (size_t)b * DD * LL;

    for (int j = tid; j < 128 * 67; j += 256) {
        int d = j / 67, i = j - d * 67;
        int idx = l0 - 3 + i;
        sA[d * PC + i] = (idx >= 0) ? src[(size_t)d * LL + idx] : 0.f;
    }
    for (int j = tid; j < 512; j += 256) swc[j] = conv_w[j];
    if (tid < 128) sbc[tid] = conv_b[tid];
    for (int j = tid; j < 1536; j += 256) swx[j] = W_xproj[j];
    for (int j = tid; j < 1024; j += 256) swd[j] = W_dt[j];
    if (tid < 128) sbd[tid] = b_dt[tid];
    __syncthreads();

    // depthwise conv + silu -> sB
    for (int j = tid; j < 128 * 64; j += 256) {
        int d = j >> 6, l = j & 63;
        float v = sbc[d];
        v += swc[d * 4 + 0] * sA[d * PC + l + 0];
        v += swc[d * 4 + 1] * sA[d * PC + l + 1];
        v += swc[d * 4 + 2] * sA[d * PC + l + 2];
        v += swc[d * 4 + 3] * sA[d * PC + l + 3];
        float sg = 1.f / (1.f + __expf(-v));
        sB[d * PC + l] = v * sg;
    }
    __syncthreads();

    // xproj: dbl[l][j]
    for (int task = tid; task < 12 * 64; task += 256) {
        int jrow = task >> 6, l = task & 63;
        const float* wr = swx + jrow * 128;
        float s = 0.f;
#pragma unroll 8
        for (int d = 0; d < 128; d++) s += sB[d * PC + l] * wr[d];
        sdbl[l * 13 + jrow] = s;
    }
    __syncthreads();

    if (tid < 128) {
        int l = tid >> 1, n = tid & 1;
        g_Cm[((size_t)b * LL + l0 + l) * 2 + n] = sdbl[l * 13 + 10 + n];
    }

    // dt -> sA
    for (int j = tid; j < 128 * 64; j += 256) {
        int d = j >> 6, l = j & 63;
        float v = sbd[d];
        const float* wr = swd + d * 8;
        const float* dr = sdbl + l * 13;
#pragma unroll
        for (int r = 0; r < 8; r++) v += dr[r] * wr[r];
        float sp = (v > 20.f) ? v : log1pf(__expf(v));
        sA[d * PC + l] = sp;
    }
    __syncthreads();

    // local scan: 2 threads per channel
    {
        const int d = tid >> 1, n = tid & 1;
        const float An = -__expf(A_log[d * 2 + n]);
        const float Dd = D_param[d];
        float h = 0.f, sd = 0.f;
        for (int l = 0; l < 64; l++) {
            float dtv = sA[d * PC + l];
            sd += dtv;
            float xv = sB[d * PC + l];
            float Bn = sdbl[l * 13 + 8 + n];
            float Cn = sdbl[l * 13 + 10 + n];
            h = __expf(An * dtv) * h + dtv * Bn * xv;
            float yn = Cn * h;
            float yo = __shfl_xor_sync(0xffffffffu, yn, 1);
            if (n == 0) {
                sB[d * PC + l] = yn + yo + xv * Dd;
                sA[d * PC + l] = sd;
            }
        }
        size_t ci = (size_t)(b * NCH + c) * 128 + d;
        if (n == 0) g_sumdt[ci] = sd;
        g_hend[ci * 2 + n] = h;
    }
    __syncthreads();

    float* dS = g_S    + (size_t)b * DD * LL + l0;
    float* dY = g_yloc + (size_t)b * DD * LL + l0;
    for (int j = tid; j < 128 * 64; j += 256) {
        int d = j >> 6, l = j & 63;
        dS[(size_t)d * LL + l] = sA[d * PC + l];
        dY[(size_t)d * LL + l] = sB[d * PC + l];
    }
}

// ================= K2.5: chunk-summary scan =================
__global__ void k25_chainscan(const float* __restrict__ A_log)
{
    int t = blockIdx.x * 256 + threadIdx.x;
    if (t >= BB * DD) return;
    int b = t >> 7, d = t & 127;
    float A1 = -__expf(A_log[d * 2 + 0]);
    float A2 = -__expf(A_log[d * 2 + 1]);
    float h1 = 0.f, h2 = 0.f;
    for (int c = 0; c < NCH; c++) {
        size_t i = (size_t)(b * NCH + c) * 128 + d;
        g_h0[i * 2 + 0] = h1;
        g_h0[i * 2 + 1] = h2;
        float sd = g_sumdt[i];
        h1 = __expf(A1 * sd) * h1 + g_hend[i * 2 + 0];
        h2 = __expf(A2 * sd) * h2 + g_hend[i * 2 + 1];
    }
}

// ================= K3: finalize y, gate, out-proj, LayerNorm =================
// 64 tokens x 128 outputs per block, 128 threads, 4 CTAs/SM
#define K3_TAH 0
#define K3_TAL 8192
#define K3_TBH 16384
#define K3_TBL 32768
#define K3_EA  49152
#define K3_SG  50176
#define K3_SBv 50688
#define K3_MU  51200
#define K3_RS  51456
#define K3_SMEM 51712
#define PO 65   // f32 epilogue pitch

__global__ __launch_bounds__(128, 4) void k3_mma(const float* __restrict__ W_out,
                                                 const float* __restrict__ A_log,
                                                 const float* __restrict__ ln_g,
                                                 const float* __restrict__ ln_b,
                                                 float* __restrict__ out)
{
    extern __shared__ char smem[];
    const uint32_t sb = smem_u32(smem);
    const int tid = threadIdx.x, wid = tid >> 5, lane = tid & 31;
    const int b = blockIdx.x >> 6;
    const int c = blockIdx.x & 63;
    const int l0 = c << 6;
    const size_t base = (size_t)b * DD * LL + l0;

    float* eA  = (float*)(smem + K3_EA);
    float* sg  = (float*)(smem + K3_SG);
    float* sbv = (float*)(smem + K3_SBv);
    float* mu  = (float*)(smem + K3_MU);
    float* rs  = (float*)(smem + K3_RS);
    if (tid < 128) {
        eA[tid] = -__expf(A_log[tid]);
        eA[tid + 128] = -__expf(A_log[tid + 128]);
        sg[tid] = ln_g[tid]; sbv[tid] = ln_b[tid];
    }
    __syncthreads();

    const int m0 = (wid & 1) * 32, n0 = (wid >> 1) * 64;
    const int rsel = lane & 15;
    const int csel = (lane >> 4) * 8;

    float acc[2][8][4];
#pragma unroll
    for (int mt = 0; mt < 2; mt++)
#pragma unroll
        for (int nt = 0; nt < 8; nt++)
#pragma unroll
            for (int q = 0; q < 4; q++) acc[mt][nt][q] = 0.f;

#pragma unroll 1
    for (int h = 0; h < 2; h++) {
        const int d0 = h << 6;
        if (h) __syncthreads();
        // stage A half: gated y[l][d]
#pragma unroll 2
        for (int j = tid; j < 2048; j += 128) {
            int l = j & 63, dp = j >> 6, d = d0 + dp * 2;
            float2 C = *(const float2*)(g_Cm + ((size_t)b * LL + l0 + l) * 2);
            float yv[2];
#pragma unroll
            for (int q = 0; q < 2; q++) {
                int dd = d + q;
                size_t g = base + (size_t)dd * LL + l;
                float yl = g_yloc[g];
                float S  = g_S[g];
                float zv = g_z[g];
                size_t hi = (size_t)(b * NCH + c) * 128 + dd;
                float h01 = g_h0[hi * 2 + 0], h02 = g_h0[hi * 2 + 1];
                float A1 = eA[dd * 2 + 0], A2 = eA[dd * 2 + 1];
                float y = yl + C.x * __expf(A1 * S) * h01 + C.y * __expf(A2 * S) * h02;
                float sig = 1.f / (1.f + __expf(-zv));
                yv[q] = y * (zv * sig);
            }
            uint32_t hi32, lo32; split_pack(yv[0], yv[1], hi32, lo32);
            uint32_t off = SWZ((uint32_t)l * 128u + (uint32_t)dp * 4u);
            *(uint32_t*)(smem + K3_TAH + off) = hi32;
            *(uint32_t*)(smem + K3_TAL + off) = lo32;
        }
        // stage B half: W_out[o][d]
#pragma unroll 4
        for (int j = tid; j < 4096; j += 128) {
            int o = j >> 5, dp = j & 31, d = d0 + dp * 2;
            float2 w = *(const float2*)(W_out + (size_t)o * 128 + d);
            uint32_t hi32, lo32; split_pack(w.x, w.y, hi32, lo32);
            uint32_t off = SWZ((uint32_t)o * 128u + (uint32_t)dp * 4u);
            *(uint32_t*)(smem + K3_TBH + off) = hi32;
            *(uint32_t*)(smem + K3_TBL + off) = lo32;
        }
        __syncthreads();

#pragma unroll 1
        for (int term = 0; term < 3; term++) {
            uint32_t ab = sb + (term == 2 ? K3_TAL : K3_TAH);
            uint32_t bb = sb + (term == 1 ? K3_TBL : K3_TBH);
#pragma unroll
            for (int ks = 0; ks < 4; ks++) {
                uint32_t kc = (uint32_t)(ks * 16 + csel) * 2u;
                uint32_t af[2][4], bfr[4][4];
#pragma unroll
                for (int mt = 0; mt < 2; mt++)
                    ldsm4(ab + SWZ((uint32_t)(m0 + mt * 16 + rsel) * 128u + kc), af[mt]);
#pragma unroll
                for (int nt2 = 0; nt2 < 4; nt2++)
                    ldsm4(bb + SWZ((uint32_t)(n0 + nt2 * 16 + rsel) * 128u + kc), bfr[nt2]);
#pragma unroll
                for (int mt = 0; mt < 2; mt++)
#pragma unroll
                    for (int nt = 0; nt < 8; nt++)
                        mma_bf16(acc[mt][nt], af[mt],
                                 bfr[nt >> 1][nt & 1], bfr[nt >> 1][(nt & 1) + 2]);
            }
        }
    }
    __syncthreads();

    // stage O[o][PO] f32 (overlays tiles)
    float* Os = (float*)smem;
    {
        int r = lane >> 2, cc = (lane & 3) * 2;
#pragma unroll
        for (int mt = 0; mt < 2; mt++)
#pragma unroll
            for (int nt = 0; nt < 8; nt++) {
                int l = m0 + mt * 16 + r, o = n0 + nt * 8 + cc;
                Os[o * PO + l]           = acc[mt][nt][0];
                Os[(o + 1) * PO + l]     = acc[mt][nt][1];
                Os[o * PO + l + 8]       = acc[mt][nt][2];
                Os[(o + 1) * PO + l + 8] = acc[mt][nt][3];
            }
    }
    __syncthreads();

    // LayerNorm stats: warp per token
    for (int l = wid; l < 64; l += 4) {
        float s = 0.f, s2 = 0.f;
#pragma unroll
        for (int o = lane; o < 128; o += 32) {
            float v = Os[o * PO + l];
            s += v; s2 += v * v;
        }
#pragma unroll
        for (int off = 16; off; off >>= 1) {
            s  += __shfl_xor_sync(0xffffffffu, s,  off);
            s2 += __shfl_xor_sync(0xffffffffu, s2, off);
        }
        if (lane == 0) {
            float m = s * (1.f / 128.f);
            mu[l] = m;
            rs[l] = rsqrtf(s2 * (1.f / 128.f) - m * m + 1e-5f);
        }
    }
    __syncthreads();

    float* op = out + base;
#pragma unroll 4
    for (int j = tid; j < 128 * 64; j += 128) {
        int o = j >> 6, l = j & 63;
        float v = (Os[o * PO + l] - mu[l]) * rs[l] * sg[o] + sbv[o];
        op[(size_t)o * LL + l] = v;
    }
}

// ---------------- launch ----------------
extern "C" void kernel_launch(void* const* d_in, const int* in_sizes, int n_in,
                              void* d_out, int out_size)
{
    const float* x1      = (const float*)d_in[0];
    const float* W_in    = (const float*)d_in[1];
    const float* conv_w  = (const float*)d_in[2];
    const float* conv_b  = (const float*)d_in[3];
    const float* W_xproj = (const float*)d_in[4];
    const float* W_dt    = (const float*)d_in[5];
    const float* b_dt    = (const float*)d_in[6];
    const float* A_log   = (const float*)d_in[7];
    const float* D_param = (const float*)d_in[8];
    const float* W_out   = (const float*)d_in[9];
    const float* ln_g    = (const float*)d_in[10];
    const float* ln_b    = (const float*)d_in[11];
    float* out = (float*)d_out;

    const int smem_k2 = (2 * 128 * PC + 64 * 13 + 512 + 128 + 1536 + 1024 + 128) * 4;

    static bool inited = false;
    if (!inited) {
        cudaFuncSetAttribute(k1_mma, cudaFuncAttributeMaxDynamicSharedMemorySize, K1_SMEM);
        cudaFuncSetAttribute(k2_chunk, cudaFuncAttributeMaxDynamicSharedMemorySize, smem_k2);
        cudaFuncSetAttribute(k3_mma, cudaFuncAttributeMaxDynamicSharedMemorySize, K3_SMEM);
        inited = true;
    }

    k1_mma<<<dim3(1024, 2), 128, K1_SMEM>>>(x1, W_in);
    k2_chunk<<<1024, 256, smem_k2>>>(conv_w, conv_b, W_xproj, W_dt, b_dt, A_log, D_param);
    k25_chainscan<<<8, 256>>>(A_log);
    k3_mma<<<1024, 128, K3_SMEM>>>(W_out, A_log, ln_g, ln_b, out);
}